// round 1
// baseline (speedup 1.0000x reference)
#include <cuda_runtime.h>
#include <cuda_bf16.h>

// TGSM fused kernel: one CTA per batch element.
// B=1024, T=256, N=14, Fd=4, H=32, K=5, C=2

#define Bn 1024
#define Tn 256
#define Nn 14
#define Hn 32

__device__ __forceinline__ float warp_sum(float v) {
    v += __shfl_xor_sync(0xffffffffu, v, 16);
    v += __shfl_xor_sync(0xffffffffu, v, 8);
    v += __shfl_xor_sync(0xffffffffu, v, 4);
    v += __shfl_xor_sync(0xffffffffu, v, 2);
    v += __shfl_xor_sync(0xffffffffu, v, 1);
    return v;
}

__global__ __launch_bounds__(128)
void tgsm_kernel(const float* __restrict__ ws,
                 const float* __restrict__ gate_w, const float* __restrict__ gate_b,
                 const float* __restrict__ gcn_w,  const float* __restrict__ gcn_b,
                 const float* __restrict__ ln_g,   const float* __restrict__ ln_b,
                 const float* __restrict__ attn_w, const float* __restrict__ attn_b,
                 const float* __restrict__ c1_w,   const float* __restrict__ c1_b,
                 const float* __restrict__ c2_w,   const float* __restrict__ c2_b,
                 const float* __restrict__ c3_w,   const float* __restrict__ c3_b,
                 float* __restrict__ out)
{
    const int b    = blockIdx.x;
    const int tid  = threadIdx.x;
    const int lane = tid & 31;
    const int wid  = tid >> 5;

    __shared__ float4 s_de[Nn];
    __shared__ float4 s_nrm[Nn];
    __shared__ float  s_esm[Nn * Nn];
    __shared__ float  s_dis[Nn];
    __shared__ float  s_r[Nn];
    __shared__ float4 s_q[Nn];
    __shared__ float4 s_p[Nn];
    __shared__ float  s_gep[4][Hn];
    __shared__ float  s_comb[5 + Hn];
    __shared__ float  s_b1[64];
    __shared__ float  s_b2[32];

    // Per-lane constant registers (lane == H channel)
    float Wc0 = gcn_w[0 * Hn + lane];
    float Wc1 = gcn_w[1 * Hn + lane];
    float Wc2 = gcn_w[2 * Hn + lane];
    float Wc3 = gcn_w[3 * Hn + lane];
    float gcnb = gcn_b[lane];
    float lng  = ln_g[lane];
    float lnb  = ln_b[lane];
    float awv  = attn_w[lane];
    float gw0  = gate_w[0];
    float gw1  = gate_w[1];
    float gbv  = gate_b[0];
    float attnb = attn_b[0];

    // init esm = 0
    for (int i = tid; i < Nn * Nn; i += 128) s_esm[i] = 0.0f;

    // online softmax state (meaningful in warp 0 only)
    float Pacc = 0.0f, Mrun = -1e30f, Srun = 0.0f;

    const float4* src = reinterpret_cast<const float4*>(ws) + (size_t)b * Tn * Nn;
    float4 de_reg = make_float4(0.f, 0.f, 0.f, 0.f);
    if (tid < Nn) de_reg = src[tid];   // prefetch t=0
    __syncthreads();

    for (int t = 0; t < Tn; t++) {
        // ---- phase 1: stage de, compute row-normalized nrm; prefetch t+1 ----
        if (tid < Nn) {
            float4 v = de_reg;
            s_de[tid] = v;
            float nn  = sqrtf(v.x*v.x + v.y*v.y + v.z*v.z + v.w*v.w);
            float inv = __fdividef(1.0f, fmaxf(nn, 1e-12f));
            s_nrm[tid] = make_float4(v.x*inv, v.y*inv, v.z*inv, v.w*inv);
            if (t + 1 < Tn) de_reg = src[(t + 1) * Nn + tid];
        }
        __syncthreads();

        // ---- phase 2: adjacency + GRU gate + esm update ----
        #pragma unroll
        for (int it = 0; it < 2; it++) {
            int i = tid + it * 128;
            if (i < Nn * Nn) {
                int n = i / Nn;
                int m = i - n * Nn;
                float4 a = s_nrm[n];
                float4 c = s_nrm[m];
                float adj = (n == m) ? 0.0f
                          : 0.5f * (a.x*c.x + a.y*c.y + a.z*c.z + a.w*c.w + 1.0f);
                float e = s_esm[i];
                float x = fmaf(gw0, e, fmaf(gw1, adj, gbv));
                float z = __fdividef(1.0f, 1.0f + __expf(-x));
                s_esm[i] = fmaf(z, adj - e, e);
            }
        }
        __syncthreads();

        // ---- phase 3: degree dis = (rowsum+1)^-1/2 ; q = dis * de ----
        if (tid < Nn) {
            float sum = 1.0f;
            #pragma unroll
            for (int m = 0; m < Nn; m++) sum += s_esm[tid * Nn + m];
            float d = rsqrtf(fmaxf(sum, 1e-6f));
            s_dis[tid] = d;
            float4 v = s_de[tid];
            s_q[tid] = make_float4(v.x*d, v.y*d, v.z*d, v.w*d);
        }
        __syncthreads();

        // ---- phase 4: p = esm @ q  (14x4), r[n] = rowsum(a_norm) ----
        if (tid < Nn * 4) {
            int n = tid >> 2, f = tid & 3;
            const float* qf = reinterpret_cast<const float*>(s_q) + f;
            float acc = 0.0f;
            #pragma unroll
            for (int m = 0; m < Nn; m++)
                acc = fmaf(s_esm[n * Nn + m], qf[4 * m], acc);
            reinterpret_cast<float*>(s_p)[tid] = acc;
        } else if (tid >= 64 && tid < 64 + Nn) {
            int n = tid - 64;
            float acc = 0.0f;
            #pragma unroll
            for (int m = 0; m < Nn; m++)
                acc = fmaf(s_esm[n * Nn + m], s_dis[m], acc);
            float d = s_dis[n];
            s_r[n] = d * (acc + d);
        }
        __syncthreads();

        // ---- phase 5: h = dis*(p+q) @ W + r*b ; LayerNorm ; ELU ; node sum ----
        float gepart = 0.0f;
        for (int n = wid; n < Nn; n += 4) {
            float4 p = s_p[n];
            float4 q = s_q[n];
            float d  = s_dis[n];
            float rr = s_r[n];
            float hv = rr * gcnb;
            hv = fmaf((p.x + q.x) * d, Wc0, hv);
            hv = fmaf((p.y + q.y) * d, Wc1, hv);
            hv = fmaf((p.z + q.z) * d, Wc2, hv);
            hv = fmaf((p.w + q.w) * d, Wc3, hv);
            // LayerNorm across lanes (H=32)
            float s1 = warp_sum(hv);
            float s2 = warp_sum(hv * hv);
            float mu  = s1 * (1.0f / 32.0f);
            float var = fmaf(-mu, mu, s2 * (1.0f / 32.0f));
            float y = (hv - mu) * rsqrtf(var + 1e-5f) * lng + lnb;
            y = (y > 0.0f) ? y : (__expf(y) - 1.0f);   // elu
            gepart += y;
        }
        s_gep[wid][lane] = gepart;
        __syncthreads();

        // ---- phase 6: ge = node mean; online softmax attention (warp 0) ----
        if (wid == 0) {
            float ge = (s_gep[0][lane] + s_gep[1][lane] +
                        s_gep[2][lane] + s_gep[3][lane]) * (1.0f / 14.0f);
            float sc = warp_sum(ge * awv) + attnb;
            float newM = fmaxf(Mrun, sc);
            float al = __expf(Mrun - newM);
            float wt = __expf(sc - newM);
            Pacc = fmaf(Pacc, al, wt * ge);
            Srun = fmaf(Srun, al, wt);
            Mrun = newM;
        }
        // no trailing barrier needed: next-step phases are fenced by B1..B4
    }

    __syncthreads();

    // ---- spectral readout: cyclic Jacobi on symmetric esm_final (warp 0) ----
    if (wid == 0) {
        for (int sweep = 0; sweep < 8; sweep++) {
            for (int p = 0; p < Nn - 1; p++) {
                for (int q = p + 1; q < Nn; q++) {
                    float apq = s_esm[p * Nn + q];
                    if (fabsf(apq) > 1e-11f) {           // uniform across warp
                        float app = s_esm[p * Nn + p];
                        float aqq = s_esm[q * Nn + q];
                        float theta = 0.5f * __fdividef(aqq - app, apq);
                        float tt = __fdividef(1.0f, fabsf(theta) + sqrtf(fmaf(theta, theta, 1.0f)));
                        if (theta < 0.0f) tt = -tt;
                        float cc = rsqrtf(fmaf(tt, tt, 1.0f));
                        float ssn = tt * cc;
                        int k = lane;
                        bool act = (k < Nn) && (k != p) && (k != q);
                        float akp = 0.f, akq = 0.f;
                        if (act) { akp = s_esm[k * Nn + p]; akq = s_esm[k * Nn + q]; }
                        __syncwarp();
                        if (act) {
                            float nkp = fmaf(cc, akp, -ssn * akq);
                            float nkq = fmaf(ssn, akp,  cc * akq);
                            s_esm[k * Nn + p] = nkp; s_esm[p * Nn + k] = nkp;
                            s_esm[k * Nn + q] = nkq; s_esm[q * Nn + k] = nkq;
                        }
                        if (lane == 0) {
                            s_esm[p * Nn + p] = fmaf(-tt, apq, app);
                            s_esm[q * Nn + q] = fmaf( tt, apq, aqq);
                            s_esm[p * Nn + q] = 0.0f;
                            s_esm[q * Nn + p] = 0.0f;
                        }
                        __syncwarp();
                    }
                }
            }
        }
        // top-K eigenvalues, ascending order (lane 0)
        if (lane == 0) {
            float ev[Nn];
            #pragma unroll
            for (int i = 0; i < Nn; i++) ev[i] = s_esm[i * Nn + i];
            for (int i = 1; i < Nn; i++) {
                float v = ev[i];
                int j = i - 1;
                while (j >= 0 && ev[j] > v) { ev[j + 1] = ev[j]; j--; }
                ev[j + 1] = v;
            }
            #pragma unroll
            for (int i = 0; i < 5; i++) s_comb[i] = ev[Nn - 5 + i];
        }
        // pooled attention output
        s_comb[5 + lane] = __fdividef(Pacc, Srun);
    }
    __syncthreads();

    // ---- classifier: 37 -> 64 (elu) -> 32 (elu) -> 2 ----
    if (tid < 64) {
        float acc = c1_b[tid];
        #pragma unroll
        for (int i = 0; i < 37; i++)
            acc = fmaf(s_comb[i], c1_w[i * 64 + tid], acc);
        s_b1[tid] = (acc > 0.0f) ? acc : (__expf(acc) - 1.0f);
    }
    __syncthreads();
    if (tid < 32) {
        float acc = c2_b[tid];
        #pragma unroll
        for (int i = 0; i < 64; i++)
            acc = fmaf(s_b1[i], c2_w[i * 32 + tid], acc);
        s_b2[tid] = (acc > 0.0f) ? acc : (__expf(acc) - 1.0f);
    }
    __syncthreads();
    if (tid < 2) {
        float acc = c3_b[tid];
        #pragma unroll
        for (int i = 0; i < 32; i++)
            acc = fmaf(s_b2[i], c3_w[i * 2 + tid], acc);
        out[b * 2 + tid] = acc;
    }
}

extern "C" void kernel_launch(void* const* d_in, const int* in_sizes, int n_in,
                              void* d_out, int out_size)
{
    const float* ws     = (const float*)d_in[0];
    const float* gate_w = (const float*)d_in[1];
    const float* gate_b = (const float*)d_in[2];
    const float* gcn_w  = (const float*)d_in[3];
    const float* gcn_b  = (const float*)d_in[4];
    const float* ln_g   = (const float*)d_in[5];
    const float* ln_b   = (const float*)d_in[6];
    const float* attn_w = (const float*)d_in[7];
    const float* attn_b = (const float*)d_in[8];
    const float* c1_w   = (const float*)d_in[9];
    const float* c1_b   = (const float*)d_in[10];
    const float* c2_w   = (const float*)d_in[11];
    const float* c2_b   = (const float*)d_in[12];
    const float* c3_w   = (const float*)d_in[13];
    const float* c3_b   = (const float*)d_in[14];
    float* out = (float*)d_out;

    tgsm_kernel<<<Bn, 128>>>(ws, gate_w, gate_b, gcn_w, gcn_b, ln_g, ln_b,
                             attn_w, attn_b, c1_w, c1_b, c2_w, c2_b,
                             c3_w, c3_b, out);
}

// round 2
// speedup vs baseline: 1.5373x; 1.5373x over previous
#include <cuda_runtime.h>
#include <cuda_bf16.h>

// TGSM fused kernel, v2: one WARP per batch element, esm in registers.
// B=1024, T=256, N=14, Fd=4, H=32, K=5, C=2

#define Bn 1024
#define Tn 256
#define Nn 14
#define Hn 32

__device__ __forceinline__ float warp_sum(float v) {
    v += __shfl_xor_sync(0xffffffffu, v, 16);
    v += __shfl_xor_sync(0xffffffffu, v, 8);
    v += __shfl_xor_sync(0xffffffffu, v, 4);
    v += __shfl_xor_sync(0xffffffffu, v, 2);
    v += __shfl_xor_sync(0xffffffffu, v, 1);
    return v;
}

__device__ __forceinline__ float elu(float y) {
    return (y > 0.0f) ? y : (__expf(y) - 1.0f);
}

__global__ __launch_bounds__(32)
void tgsm_kernel(const float* __restrict__ ws,
                 const float* __restrict__ gate_w, const float* __restrict__ gate_b,
                 const float* __restrict__ gcn_w,  const float* __restrict__ gcn_b,
                 const float* __restrict__ ln_g,   const float* __restrict__ ln_b,
                 const float* __restrict__ attn_w, const float* __restrict__ attn_b,
                 const float* __restrict__ c1_w,   const float* __restrict__ c1_b,
                 const float* __restrict__ c2_w,   const float* __restrict__ c2_b,
                 const float* __restrict__ c3_w,   const float* __restrict__ c3_b,
                 float* __restrict__ out)
{
    const int b    = blockIdx.x;
    const int lane = threadIdx.x;   // 0..31

    __shared__ float4 s_de[Nn];
    __shared__ float  s_inv[Nn];
    __shared__ float4 s_q[Nn];
    __shared__ float  s_dis[Nn];
    __shared__ float4 s_xp[Nn];     // x * invstd (per node)
    __shared__ float2 s_mr[Nn];     // (rr*invstd, mu*invstd)
    __shared__ float  s_esm[Nn * Nn];
    __shared__ float  s_comb[5 + Hn];
    __shared__ float  s_b1[64];

    // ---- per-lane constants (lane == H channel) ----
    float Wc0 = gcn_w[0 * Hn + lane];
    float Wc1 = gcn_w[1 * Hn + lane];
    float Wc2 = gcn_w[2 * Hn + lane];
    float Wc3 = gcn_w[3 * Hn + lane];
    float gcnb = gcn_b[lane];
    float lng  = ln_g[lane];
    float lnb  = ln_b[lane];
    float awv  = attn_w[lane];
    float gw0  = gate_w[0];
    float gw1  = gate_w[1];
    float gbv  = gate_b[0];
    float attnb = attn_b[0];

    // ---- closed-form LN statistics precompute ----
    // SW_f = sum_h W[f][h], Sb = sum_h b[h], G = Wtilde Wtilde^T (5x5 sym)
    float SW0 = warp_sum(Wc0);
    float SW1 = warp_sum(Wc1);
    float SW2 = warp_sum(Wc2);
    float SW3 = warp_sum(Wc3);
    float Sb  = warp_sum(gcnb);
    float vW[5] = {Wc0, Wc1, Wc2, Wc3, gcnb};
    float G[5][5];
    #pragma unroll
    for (int i = 0; i < 5; i++) {
        #pragma unroll
        for (int j = i; j < 5; j++) {
            float g = warp_sum(vW[i] * vW[j]);
            G[i][j] = g;
            G[j][i] = g;
        }
    }

    // ---- register-resident esm: lane m holds column m (== row m by symmetry) ----
    float e[Nn];
    #pragma unroll
    for (int i = 0; i < Nn; i++) e[i] = 0.0f;

    // online-softmax attention state (lane == H channel)
    float Pacc = 0.0f, Mrun = -1e30f, Srun = 0.0f;

    const float4* src = reinterpret_cast<const float4*>(ws) + (size_t)b * Tn * Nn;
    float4 dnext = make_float4(0.f, 0.f, 0.f, 0.f);
    if (lane < Nn) dnext = src[lane];

    for (int t = 0; t < Tn; t++) {
        // ---- stage de + inv-norm; prefetch next ----
        float4 de = dnext;
        float inv = 0.0f;
        if (lane < Nn) {
            float d2 = de.x*de.x + de.y*de.y + de.z*de.z + de.w*de.w;
            float nn = sqrtf(d2);
            inv = __fdividef(1.0f, fmaxf(nn, 1e-12f));
            s_de[lane]  = de;
            s_inv[lane] = inv;
            if (t + 1 < Tn) dnext = src[(t + 1) * Nn + lane];
        }
        __syncwarp();

        // ---- adjacency + GRU gate + esm update + rowsum (lane = column m) ----
        float rowsum = 1.0f;   // +1 for identity diag
        #pragma unroll
        for (int n = 0; n < Nn; n++) {
            float4 dn  = s_de[n];
            float invn = s_inv[n];
            float dot = de.x*dn.x + de.y*dn.y + de.z*dn.z + de.w*dn.w;
            float adj = fmaf(dot * inv, invn * 0.5f, 0.5f);
            if (n == lane) adj = 0.0f;
            float ee = e[n];
            float x  = fmaf(gw0, ee, fmaf(gw1, adj, gbv));
            float z  = __fdividef(1.0f, 1.0f + __expf(-x));
            ee = fmaf(z, adj - ee, ee);
            e[n] = ee;
            rowsum += ee;
        }
        float dis = rsqrtf(fmaxf(rowsum, 1e-6f));
        if (lane < Nn) {
            s_q[lane]   = make_float4(de.x*dis, de.y*dis, de.z*dis, de.w*dis);
            s_dis[lane] = dis;
        }
        __syncwarp();

        // ---- p = esm @ q (row = lane), r = rowsum(a_norm) ----
        float4 p = make_float4(0.f, 0.f, 0.f, 0.f);
        float racc = 0.0f;
        #pragma unroll
        for (int m = 0; m < Nn; m++) {
            float4 qm = s_q[m];
            float dm  = s_dis[m];
            float em  = e[m];
            p.x = fmaf(em, qm.x, p.x);
            p.y = fmaf(em, qm.y, p.y);
            p.z = fmaf(em, qm.z, p.z);
            p.w = fmaf(em, qm.w, p.w);
            racc = fmaf(em, dm, racc);
        }
        if (lane < Nn) {
            float rr = dis * (racc + dis);
            float x0 = (p.x + de.x * dis) * dis;
            float x1 = (p.y + de.y * dis) * dis;
            float x2 = (p.z + de.z * dis) * dis;
            float x3 = (p.w + de.w * dis) * dis;
            // LN stats in closed form
            float mu = (x0*SW0 + x1*SW1 + x2*SW2 + x3*SW3 + rr*Sb) * (1.0f/32.0f);
            float xt[5] = {x0, x1, x2, x3, rr};
            float s2 = 0.0f;
            #pragma unroll
            for (int i = 0; i < 5; i++) {
                float rowd = 0.0f;
                #pragma unroll
                for (int j = 0; j < 5; j++) rowd = fmaf(G[i][j], xt[j], rowd);
                s2 = fmaf(xt[i], rowd, s2);
            }
            s2 *= (1.0f/32.0f);
            float var  = fmaf(-mu, mu, s2);
            float istd = rsqrtf(var + 1e-5f);
            s_xp[lane] = make_float4(x0*istd, x1*istd, x2*istd, x3*istd);
            s_mr[lane] = make_float2(rr*istd, mu*istd);
        }
        __syncwarp();

        // ---- per-channel LN apply + ELU + node mean (lane = H channel) ----
        float ge = 0.0f;
        #pragma unroll
        for (int n = 0; n < Nn; n++) {
            float4 xp = s_xp[n];
            float2 mr = s_mr[n];
            float hv = -mr.y;
            hv = fmaf(xp.x, Wc0, hv);
            hv = fmaf(xp.y, Wc1, hv);
            hv = fmaf(xp.z, Wc2, hv);
            hv = fmaf(xp.w, Wc3, hv);
            hv = fmaf(mr.x, gcnb, hv);
            float y = fmaf(hv, lng, lnb);
            ge += elu(y);
        }
        ge *= (1.0f / 14.0f);

        // ---- online softmax attention pooling ----
        float sc = warp_sum(ge * awv) + attnb;
        float newM = fmaxf(Mrun, sc);
        float al = __expf(Mrun - newM);
        float wt = __expf(sc - newM);
        Pacc = fmaf(Pacc, al, wt * ge);
        Srun = fmaf(Srun, al, wt);
        Mrun = newM;
        // no extra syncwarp needed: next-step hazards covered by the 3 above
    }

    // ---- dump esm to shared for Jacobi ----
    if (lane < Nn) {
        #pragma unroll
        for (int n = 0; n < Nn; n++) s_esm[n * Nn + lane] = e[n];
    }
    __syncwarp();

    // ---- cyclic Jacobi eigensolver (whole warp) ----
    for (int sweep = 0; sweep < 8; sweep++) {
        for (int pp = 0; pp < Nn - 1; pp++) {
            for (int qq = pp + 1; qq < Nn; qq++) {
                float apq = s_esm[pp * Nn + qq];
                if (fabsf(apq) > 1e-11f) {            // warp-uniform
                    float app = s_esm[pp * Nn + pp];
                    float aqq = s_esm[qq * Nn + qq];
                    float theta = 0.5f * __fdividef(aqq - app, apq);
                    float tt = __fdividef(1.0f, fabsf(theta) + sqrtf(fmaf(theta, theta, 1.0f)));
                    if (theta < 0.0f) tt = -tt;
                    float cc  = rsqrtf(fmaf(tt, tt, 1.0f));
                    float ssn = tt * cc;
                    int k = lane;
                    bool act = (k < Nn) && (k != pp) && (k != qq);
                    float akp = 0.f, akq = 0.f;
                    if (act) { akp = s_esm[k * Nn + pp]; akq = s_esm[k * Nn + qq]; }
                    __syncwarp();
                    if (act) {
                        float nkp = fmaf(cc, akp, -ssn * akq);
                        float nkq = fmaf(ssn, akp,  cc * akq);
                        s_esm[k * Nn + pp] = nkp; s_esm[pp * Nn + k] = nkp;
                        s_esm[k * Nn + qq] = nkq; s_esm[qq * Nn + k] = nkq;
                    }
                    if (lane == 0) {
                        s_esm[pp * Nn + pp] = fmaf(-tt, apq, app);
                        s_esm[qq * Nn + qq] = fmaf( tt, apq, aqq);
                        s_esm[pp * Nn + qq] = 0.0f;
                        s_esm[qq * Nn + pp] = 0.0f;
                    }
                    __syncwarp();
                }
            }
        }
    }

    // top-5 eigenvalues (ascending) + pooled attention -> combined vector
    if (lane == 0) {
        float ev[Nn];
        #pragma unroll
        for (int i = 0; i < Nn; i++) ev[i] = s_esm[i * Nn + i];
        for (int i = 1; i < Nn; i++) {
            float v = ev[i];
            int j = i - 1;
            while (j >= 0 && ev[j] > v) { ev[j + 1] = ev[j]; j--; }
            ev[j + 1] = v;
        }
        #pragma unroll
        for (int i = 0; i < 5; i++) s_comb[i] = ev[Nn - 5 + i];
    }
    s_comb[5 + lane] = __fdividef(Pacc, Srun);
    __syncwarp();

    // ---- classifier: 37 -> 64 (elu) -> 32 (elu) -> 2 ----
    {
        float a0 = c1_b[lane];
        float a1 = c1_b[lane + 32];
        #pragma unroll
        for (int i = 0; i < 37; i++) {
            float ci = s_comb[i];
            a0 = fmaf(ci, c1_w[i * 64 + lane], a0);
            a1 = fmaf(ci, c1_w[i * 64 + 32 + lane], a1);
        }
        s_b1[lane]      = elu(a0);
        s_b1[lane + 32] = elu(a1);
    }
    __syncwarp();
    {
        float a2 = c2_b[lane];
        #pragma unroll
        for (int i = 0; i < 64; i++)
            a2 = fmaf(s_b1[i], c2_w[i * 32 + lane], a2);
        float h2 = elu(a2);
        float r0 = warp_sum(h2 * c3_w[lane * 2 + 0]);
        float r1 = warp_sum(h2 * c3_w[lane * 2 + 1]);
        if (lane == 0) {
            out[b * 2 + 0] = r0 + c3_b[0];
            out[b * 2 + 1] = r1 + c3_b[1];
        }
    }
}

extern "C" void kernel_launch(void* const* d_in, const int* in_sizes, int n_in,
                              void* d_out, int out_size)
{
    const float* ws     = (const float*)d_in[0];
    const float* gate_w = (const float*)d_in[1];
    const float* gate_b = (const float*)d_in[2];
    const float* gcn_w  = (const float*)d_in[3];
    const float* gcn_b  = (const float*)d_in[4];
    const float* ln_g   = (const float*)d_in[5];
    const float* ln_b   = (const float*)d_in[6];
    const float* attn_w = (const float*)d_in[7];
    const float* attn_b = (const float*)d_in[8];
    const float* c1_w   = (const float*)d_in[9];
    const float* c1_b   = (const float*)d_in[10];
    const float* c2_w   = (const float*)d_in[11];
    const float* c2_b   = (const float*)d_in[12];
    const float* c3_w   = (const float*)d_in[13];
    const float* c3_b   = (const float*)d_in[14];
    float* out = (float*)d_out;

    tgsm_kernel<<<Bn, 32>>>(ws, gate_w, gate_b, gcn_w, gcn_b, ln_g, ln_b,
                            attn_w, attn_b, c1_w, c1_b, c2_w, c2_b,
                            c3_w, c3_b, out);
}